// round 5
// baseline (speedup 1.0000x reference)
#include <cuda_runtime.h>
#include <math.h>

#define N_NODES 100000
#define N_EDGES 3200000
#define F_IN 64
#define F_H 16

// ---------------- scratch (device globals: sanctioned, no runtime alloc) ----
__device__ int    g_src[N_EDGES];
__device__ int    g_dst[N_EDGES];
__device__ float  g_norm[N_EDGES];
__device__ float  g_deg[N_NODES];
__device__ float  g_dinv[N_NODES];
__device__ float4 g_h1[N_NODES * 4];   // linear-1 output  [n,16]
__device__ float4 g_a1[N_NODES * 4];   // aggregated layer-1 out
__device__ float4 g_h2[N_NODES * 4];   // linear-2 output
__device__ float4 g_a2[N_NODES * 4];   // aggregated layer-2 out
__device__ float  g_c[N_NODES];        // linear-3 per-node scalar
__device__ float  g_hsum[16];          // sum of relu(a2) over nodes
__device__ float  g_part[256];         // block partials (max / sum)
__device__ float  g_smax;
__device__ float  g_sinv;
__device__ int    g_is64;

// ---------------- helpers ----------------------------------------------------
__device__ __forceinline__ void red_add_v4(float* p, float4 v) {
    asm volatile("red.global.add.v4.f32 [%0], {%1,%2,%3,%4};"
                 :: "l"(p), "f"(v.x), "f"(v.y), "f"(v.z), "f"(v.w)
                 : "memory");
}
__device__ __forceinline__ float warpMax(float v) {
    #pragma unroll
    for (int o = 16; o; o >>= 1) v = fmaxf(v, __shfl_xor_sync(0xffffffffu, v, o));
    return v;
}
__device__ __forceinline__ float warpSum(float v) {
    #pragma unroll
    for (int o = 16; o; o >>= 1) v += __shfl_xor_sync(0xffffffffu, v, o);
    return v;
}

// ---------------- kernels ----------------------------------------------------

// Detect whether the edge buffer is int64 (odd int32 words all zero) or int32.
__global__ void k_detect(const int* __restrict__ ed) {
    if (threadIdx.x == 0) {
        int is64 = 1;
        for (int i = 0; i < 64; i++)
            if (ed[2 * i + 1] != 0) { is64 = 0; break; }
        g_is64 = is64;
    }
}

__global__ void k_init() {
    int i = blockIdx.x * blockDim.x + threadIdx.x;
    if (i < N_NODES) g_deg[i] = 1.0f;    // self-loop weight
    if (i < 16)      g_hsum[i] = 0.0f;
}

// deg scatter + int32 conversion of edge lists
__global__ void k_deg(const int* __restrict__ ed, const float* __restrict__ w) {
    int e = blockIdx.x * blockDim.x + threadIdx.x;
    if (e >= N_EDGES) return;
    int s, d;
    if (g_is64) {
        const long long* e64 = (const long long*)ed;
        s = (int)e64[e];
        d = (int)e64[N_EDGES + e];
    } else {
        s = ed[e];
        d = ed[N_EDGES + e];
    }
    g_src[e] = s;
    g_dst[e] = d;
    atomicAdd(&g_deg[d], w[e]);
}

__global__ void k_dinv() {
    int i = blockIdx.x * blockDim.x + threadIdx.x;
    if (i < N_NODES) g_dinv[i] = rsqrtf(g_deg[i]);
}

__global__ void k_norm(const float* __restrict__ w) {
    int e = blockIdx.x * blockDim.x + threadIdx.x;
    if (e < N_EDGES)
        g_norm[e] = g_dinv[g_src[e]] * w[e] * g_dinv[g_dst[e]];
}

// linear 1: h1 = x @ W1^T ; a1 init = b1 + dinv^2 * h1 (self loop)
__global__ void k_lin1(const float* __restrict__ x, const float* __restrict__ W1,
                       const float* __restrict__ b1) {
    __shared__ float sx[16][65];
    __shared__ float sW[16][65];
    int t = threadIdx.x;                 // 256 threads, 16 nodes/block
    int node0 = blockIdx.x * 16;
    for (int i = t; i < 16 * 64; i += 256) sW[i >> 6][i & 63] = W1[i];
    const float* xb = x + (size_t)node0 * 64;
    for (int i = t; i < 16 * 64; i += 256) sx[i >> 6][i & 63] = xb[i];
    __syncthreads();
    int ni = t >> 4, j = t & 15;
    float acc = 0.0f;
    #pragma unroll
    for (int k = 0; k < 64; k++) acc += sx[ni][k] * sW[j][k];
    int node = node0 + ni;
    ((float*)g_h1)[node * 16 + j] = acc;
    float di = g_dinv[node];
    ((float*)g_a1)[node * 16 + j] = b1[j] + di * di * acc;
}

// edge aggregation, 4 threads per edge, vector-reduction stores. L selects layer.
template <int L>
__global__ void k_agg16() {
    int idx = blockIdx.x * blockDim.x + threadIdx.x;   // 4*E threads exactly
    int e = idx >> 2, q = idx & 3;
    int s = g_src[e], d = g_dst[e];
    float nm = g_norm[e];
    float4 v = (L == 1 ? g_h1 : g_h2)[s * 4 + q];
    v.x *= nm; v.y *= nm; v.z *= nm; v.w *= nm;
    red_add_v4((float*)&((L == 1 ? g_a1 : g_a2)[d * 4 + q]), v);
}

// linear 2: h2 = relu(a1) @ W2^T ; a2 init = b2 + dinv^2 * h2
__global__ void k_lin2(const float* __restrict__ W2, const float* __restrict__ b2) {
    __shared__ float sa[16][17];
    __shared__ float sW[16][17];
    int t = threadIdx.x;
    int node0 = blockIdx.x * 16;
    sW[t >> 4][t & 15] = W2[t];
    float v = ((const float*)g_a1)[node0 * 16 + t];
    sa[t >> 4][t & 15] = v > 0.0f ? v : 0.0f;
    __syncthreads();
    int ni = t >> 4, j = t & 15;
    float acc = 0.0f;
    #pragma unroll
    for (int k = 0; k < 16; k++) acc += sa[ni][k] * sW[j][k];
    int node = node0 + ni;
    ((float*)g_h2)[node * 16 + j] = acc;
    float di = g_dinv[node];
    ((float*)g_a2)[node * 16 + j] = b2[j] + di * di * acc;
}

// linear 3: c = relu(a2) @ W3^T ; out init = b3 + dinv^2*c ; also hsum reduce
__global__ void k_lin3(const float* __restrict__ W3, const float* __restrict__ b3,
                       float* __restrict__ out) {
    __shared__ float sW3[16];
    __shared__ float sh[16];
    int t = threadIdx.x;
    if (t < 16) { sW3[t] = W3[t]; sh[t] = 0.0f; }
    __syncthreads();
    int i = blockIdx.x * blockDim.x + t;
    float hv[16];
    if (i < N_NODES) {
        float c = 0.0f;
        #pragma unroll
        for (int q = 0; q < 4; q++) {
            float4 v = g_a2[i * 4 + q];
            v.x = fmaxf(v.x, 0.0f); v.y = fmaxf(v.y, 0.0f);
            v.z = fmaxf(v.z, 0.0f); v.w = fmaxf(v.w, 0.0f);
            hv[q * 4 + 0] = v.x; hv[q * 4 + 1] = v.y;
            hv[q * 4 + 2] = v.z; hv[q * 4 + 3] = v.w;
            c += v.x * sW3[q * 4 + 0] + v.y * sW3[q * 4 + 1]
               + v.z * sW3[q * 4 + 2] + v.w * sW3[q * 4 + 3];
        }
        g_c[i] = c;
        float di = g_dinv[i];
        out[i] = b3[0] + di * di * c;
    } else {
        #pragma unroll
        for (int k = 0; k < 16; k++) hv[k] = 0.0f;
    }
    #pragma unroll
    for (int k = 0; k < 16; k++) {
        float v = warpSum(hv[k]);
        if ((t & 31) == 0) atomicAdd(&sh[k], v);
    }
    __syncthreads();
    if (t < 16) atomicAdd(&g_hsum[t], sh[t]);
}

// layer-3 edge aggregation (scalar)
__global__ void k_agg3(float* __restrict__ out) {
    int e = blockIdx.x * blockDim.x + threadIdx.x;
    if (e < N_EDGES)
        atomicAdd(&out[g_dst[e]], g_norm[e] * g_c[g_src[e]]);
}

__global__ void k_max(const float* __restrict__ c) {
    __shared__ float sm[8];
    int t = threadIdx.x;
    float m = -3.4e38f;
    for (int i = blockIdx.x * blockDim.x + t; i < N_NODES; i += gridDim.x * blockDim.x)
        m = fmaxf(m, c[i]);
    m = warpMax(m);
    if ((t & 31) == 0) sm[t >> 5] = m;
    __syncthreads();
    if (t < 32) {
        m = (t < 8) ? sm[t] : -3.4e38f;
        m = warpMax(m);
        if (t == 0) g_part[blockIdx.x] = m;
    }
}

__global__ void k_maxfin() {
    __shared__ float sm[4];
    int t = threadIdx.x;                 // 128 threads
    float m = warpMax(g_part[t]);
    if ((t & 31) == 0) sm[t >> 5] = m;
    __syncthreads();
    if (t == 0) g_smax = fmaxf(fmaxf(sm[0], sm[1]), fmaxf(sm[2], sm[3]));
}

__global__ void k_exp(float* __restrict__ c) {
    __shared__ float sm[8];
    int t = threadIdx.x;
    float mx = g_smax;
    float s = 0.0f;
    for (int i = blockIdx.x * blockDim.x + t; i < N_NODES; i += gridDim.x * blockDim.x) {
        float e = expf(c[i] - mx);
        c[i] = e;
        s += e;
    }
    s = warpSum(s);
    if ((t & 31) == 0) sm[t >> 5] = s;
    __syncthreads();
    if (t < 32) {
        s = (t < 8) ? sm[t] : 0.0f;
        s = warpSum(s);
        if (t == 0) g_part[blockIdx.x] = s;
    }
}

__global__ void k_sumfin(const float* __restrict__ A2w, const float* __restrict__ A2b,
                         float* __restrict__ out) {
    __shared__ float sm[4];
    int t = threadIdx.x;                 // 128 threads
    float s = warpSum(g_part[t]);
    if ((t & 31) == 0) sm[t >> 5] = s;
    __syncthreads();
    if (t == 0) {
        float total = sm[0] + sm[1] + sm[2] + sm[3];
        g_sinv = 1.0f / total;
        float val = A2b[0];
        const float invn = 1.0f / (float)N_NODES;
        #pragma unroll
        for (int k = 0; k < 16; k++) val += g_hsum[k] * invn * A2w[k];
        out[N_NODES] = val;              // value head
    }
}

__global__ void k_scale(float* __restrict__ out) {
    int i = blockIdx.x * blockDim.x + threadIdx.x;
    if (i < N_NODES) out[i] *= g_sinv;
}

// ---------------- launch ------------------------------------------------------
extern "C" void kernel_launch(void* const* d_in, const int* in_sizes, int n_in,
                              void* d_out, int out_size) {
    const float* x   = (const float*)d_in[0];
    const int*   ed  = (const int*)d_in[1];
    const float* w   = (const float*)d_in[2];
    const float* W1  = (const float*)d_in[3];
    const float* b1  = (const float*)d_in[4];
    const float* W2  = (const float*)d_in[5];
    const float* b2  = (const float*)d_in[6];
    const float* W3  = (const float*)d_in[7];
    const float* b3  = (const float*)d_in[8];
    const float* A2w = (const float*)d_in[9];
    const float* A2b = (const float*)d_in[10];
    float* out = (float*)d_out;

    (void)in_sizes; (void)n_in; (void)out_size;

    k_detect<<<1, 32>>>(ed);
    k_init<<<(N_NODES + 255) / 256, 256>>>();
    k_deg<<<N_EDGES / 256, 256>>>(ed, w);
    k_dinv<<<(N_NODES + 255) / 256, 256>>>();
    k_norm<<<N_EDGES / 256, 256>>>(w);

    k_lin1<<<N_NODES / 16, 256>>>(x, W1, b1);
    k_agg16<1><<<(N_EDGES * 4) / 256, 256>>>();

    k_lin2<<<N_NODES / 16, 256>>>(W2, b2);
    k_agg16<2><<<(N_EDGES * 4) / 256, 256>>>();

    k_lin3<<<(N_NODES + 255) / 256, 256>>>(W3, b3, out);
    k_agg3<<<N_EDGES / 256, 256>>>(out);

    k_max<<<128, 256>>>(out);
    k_maxfin<<<1, 128>>>();
    k_exp<<<128, 256>>>(out);
    k_sumfin<<<1, 128>>>(A2w, A2b, out);
    k_scale<<<(N_NODES + 255) / 256, 256>>>(out);
}

// round 6
// speedup vs baseline: 1.4911x; 1.4911x over previous
#include <cuda_runtime.h>
#include <math.h>

#define N_NODES 100000
#define N_EDGES 3200000
#define F_IN 64
#define F_H 16

// ---------------- scratch (device globals: sanctioned, no runtime alloc) ----
__device__ int    g_src[N_EDGES];
__device__ int    g_dst[N_EDGES];
__device__ float  g_norm[N_EDGES];
__device__ float  g_deg[N_NODES];
__device__ float  g_dinv[N_NODES];
__device__ float4 g_h1[N_NODES * 4];   // linear-1 output  [n,16]
__device__ float4 g_a1[N_NODES * 4];   // aggregated layer-1 out
__device__ float4 g_h2[N_NODES * 4];   // linear-2 output
__device__ float4 g_a2[N_NODES * 4];   // aggregated layer-2 out
__device__ float  g_c[N_NODES];        // linear-3 per-node scalar
__device__ float  g_hsum[16];          // sum of relu(a2) over nodes
__device__ float  g_part[256];         // block partials (max / sum)
__device__ float  g_smax;
__device__ float  g_sinv;
__device__ int    g_is64;

// ---------------- helpers ----------------------------------------------------
__device__ __forceinline__ void red_add_v4(float* p, float4 v) {
    asm volatile("red.global.add.v4.f32 [%0], {%1,%2,%3,%4};"
                 :: "l"(p), "f"(v.x), "f"(v.y), "f"(v.z), "f"(v.w)
                 : "memory");
}
__device__ __forceinline__ float warpMax(float v) {
    #pragma unroll
    for (int o = 16; o; o >>= 1) v = fmaxf(v, __shfl_xor_sync(0xffffffffu, v, o));
    return v;
}
__device__ __forceinline__ float warpSum(float v) {
    #pragma unroll
    for (int o = 16; o; o >>= 1) v += __shfl_xor_sync(0xffffffffu, v, o);
    return v;
}

// ---------------- kernels ----------------------------------------------------

// Detect whether the edge buffer is int64 (odd int32 words all zero) or int32.
__global__ void k_detect(const int* __restrict__ ed) {
    if (threadIdx.x == 0) {
        int is64 = 1;
        for (int i = 0; i < 64; i++)
            if (ed[2 * i + 1] != 0) { is64 = 0; break; }
        g_is64 = is64;
    }
}

__global__ void k_init() {
    int i = blockIdx.x * blockDim.x + threadIdx.x;
    if (i < N_NODES) g_deg[i] = 1.0f;    // self-loop weight
    if (i < 16)      g_hsum[i] = 0.0f;
}

// deg scatter + int32 conversion of edge lists
__global__ void k_deg(const int* __restrict__ ed, const float* __restrict__ w) {
    int e = blockIdx.x * blockDim.x + threadIdx.x;
    if (e >= N_EDGES) return;
    int s, d;
    if (g_is64) {
        const long long* e64 = (const long long*)ed;
        s = (int)e64[e];
        d = (int)e64[N_EDGES + e];
    } else {
        s = ed[e];
        d = ed[N_EDGES + e];
    }
    g_src[e] = s;
    g_dst[e] = d;
    atomicAdd(&g_deg[d], w[e]);
}

__global__ void k_dinv() {
    int i = blockIdx.x * blockDim.x + threadIdx.x;
    if (i < N_NODES) g_dinv[i] = rsqrtf(g_deg[i]);
}

__global__ void k_norm(const float* __restrict__ w) {
    int e = blockIdx.x * blockDim.x + threadIdx.x;
    if (e < N_EDGES)
        g_norm[e] = g_dinv[g_src[e]] * w[e] * g_dinv[g_dst[e]];
}

// linear 1: h1 = x @ W1^T ; a1 init = b1 + dinv^2 * h1 (self loop)
__global__ void k_lin1(const float* __restrict__ x, const float* __restrict__ W1,
                       const float* __restrict__ b1) {
    __shared__ float sx[16][65];
    __shared__ float sW[16][65];
    int t = threadIdx.x;                 // 256 threads, 16 nodes/block
    int node0 = blockIdx.x * 16;
    for (int i = t; i < 16 * 64; i += 256) sW[i >> 6][i & 63] = W1[i];
    const float* xb = x + (size_t)node0 * 64;
    for (int i = t; i < 16 * 64; i += 256) sx[i >> 6][i & 63] = xb[i];
    __syncthreads();
    int ni = t >> 4, j = t & 15;
    float acc = 0.0f;
    #pragma unroll
    for (int k = 0; k < 64; k++) acc += sx[ni][k] * sW[j][k];
    int node = node0 + ni;
    ((float*)g_h1)[node * 16 + j] = acc;
    float di = g_dinv[node];
    ((float*)g_a1)[node * 16 + j] = b1[j] + di * di * acc;
}

// edge aggregation, 4 threads per edge, vector-reduction stores. L selects layer.
template <int L>
__global__ void k_agg16() {
    int idx = blockIdx.x * blockDim.x + threadIdx.x;   // 4*E threads exactly
    int e = idx >> 2, q = idx & 3;
    int s = g_src[e], d = g_dst[e];
    float nm = g_norm[e];
    float4 v = (L == 1 ? g_h1 : g_h2)[s * 4 + q];
    v.x *= nm; v.y *= nm; v.z *= nm; v.w *= nm;
    red_add_v4((float*)&((L == 1 ? g_a1 : g_a2)[d * 4 + q]), v);
}

// linear 2: h2 = relu(a1) @ W2^T ; a2 init = b2 + dinv^2 * h2
__global__ void k_lin2(const float* __restrict__ W2, const float* __restrict__ b2) {
    __shared__ float sa[16][17];
    __shared__ float sW[16][17];
    int t = threadIdx.x;
    int node0 = blockIdx.x * 16;
    sW[t >> 4][t & 15] = W2[t];
    float v = ((const float*)g_a1)[node0 * 16 + t];
    sa[t >> 4][t & 15] = v > 0.0f ? v : 0.0f;
    __syncthreads();
    int ni = t >> 4, j = t & 15;
    float acc = 0.0f;
    #pragma unroll
    for (int k = 0; k < 16; k++) acc += sa[ni][k] * sW[j][k];
    int node = node0 + ni;
    ((float*)g_h2)[node * 16 + j] = acc;
    float di = g_dinv[node];
    ((float*)g_a2)[node * 16 + j] = b2[j] + di * di * acc;
}

// linear 3: c = relu(a2) @ W3^T ; out init = b3 + dinv^2*c ; also hsum reduce
__global__ void k_lin3(const float* __restrict__ W3, const float* __restrict__ b3,
                       float* __restrict__ out) {
    __shared__ float sW3[16];
    __shared__ float sh[16];
    int t = threadIdx.x;
    if (t < 16) { sW3[t] = W3[t]; sh[t] = 0.0f; }
    __syncthreads();
    int i = blockIdx.x * blockDim.x + t;
    float hv[16];
    if (i < N_NODES) {
        float c = 0.0f;
        #pragma unroll
        for (int q = 0; q < 4; q++) {
            float4 v = g_a2[i * 4 + q];
            v.x = fmaxf(v.x, 0.0f); v.y = fmaxf(v.y, 0.0f);
            v.z = fmaxf(v.z, 0.0f); v.w = fmaxf(v.w, 0.0f);
            hv[q * 4 + 0] = v.x; hv[q * 4 + 1] = v.y;
            hv[q * 4 + 2] = v.z; hv[q * 4 + 3] = v.w;
            c += v.x * sW3[q * 4 + 0] + v.y * sW3[q * 4 + 1]
               + v.z * sW3[q * 4 + 2] + v.w * sW3[q * 4 + 3];
        }
        g_c[i] = c;
        float di = g_dinv[i];
        out[i] = b3[0] + di * di * c;
    } else {
        #pragma unroll
        for (int k = 0; k < 16; k++) hv[k] = 0.0f;
    }
    #pragma unroll
    for (int k = 0; k < 16; k++) {
        float v = warpSum(hv[k]);
        if ((t & 31) == 0) atomicAdd(&sh[k], v);
    }
    __syncthreads();
    if (t < 16) atomicAdd(&g_hsum[t], sh[t]);
}

// layer-3 edge aggregation (scalar)
__global__ void k_agg3(float* __restrict__ out) {
    int e = blockIdx.x * blockDim.x + threadIdx.x;
    if (e < N_EDGES)
        atomicAdd(&out[g_dst[e]], g_norm[e] * g_c[g_src[e]]);
}

__global__ void k_max(const float* __restrict__ c) {
    __shared__ float sm[8];
    int t = threadIdx.x;
    float m = -3.4e38f;
    for (int i = blockIdx.x * blockDim.x + t; i < N_NODES; i += gridDim.x * blockDim.x)
        m = fmaxf(m, c[i]);
    m = warpMax(m);
    if ((t & 31) == 0) sm[t >> 5] = m;
    __syncthreads();
    if (t < 32) {
        m = (t < 8) ? sm[t] : -3.4e38f;
        m = warpMax(m);
        if (t == 0) g_part[blockIdx.x] = m;
    }
}

__global__ void k_maxfin() {
    __shared__ float sm[4];
    int t = threadIdx.x;                 // 128 threads
    float m = warpMax(g_part[t]);
    if ((t & 31) == 0) sm[t >> 5] = m;
    __syncthreads();
    if (t == 0) g_smax = fmaxf(fmaxf(sm[0], sm[1]), fmaxf(sm[2], sm[3]));
}

__global__ void k_exp(float* __restrict__ c) {
    __shared__ float sm[8];
    int t = threadIdx.x;
    float mx = g_smax;
    float s = 0.0f;
    for (int i = blockIdx.x * blockDim.x + t; i < N_NODES; i += gridDim.x * blockDim.x) {
        float e = expf(c[i] - mx);
        c[i] = e;
        s += e;
    }
    s = warpSum(s);
    if ((t & 31) == 0) sm[t >> 5] = s;
    __syncthreads();
    if (t < 32) {
        s = (t < 8) ? sm[t] : 0.0f;
        s = warpSum(s);
        if (t == 0) g_part[blockIdx.x] = s;
    }
}

__global__ void k_sumfin(const float* __restrict__ A2w, const float* __restrict__ A2b,
                         float* __restrict__ out) {
    __shared__ float sm[4];
    int t = threadIdx.x;                 // 128 threads
    float s = warpSum(g_part[t]);
    if ((t & 31) == 0) sm[t >> 5] = s;
    __syncthreads();
    if (t == 0) {
        float total = sm[0] + sm[1] + sm[2] + sm[3];
        g_sinv = 1.0f / total;
        float val = A2b[0];
        const float invn = 1.0f / (float)N_NODES;
        #pragma unroll
        for (int k = 0; k < 16; k++) val += g_hsum[k] * invn * A2w[k];
        out[N_NODES] = val;              // value head
    }
}

__global__ void k_scale(float* __restrict__ out) {
    int i = blockIdx.x * blockDim.x + threadIdx.x;
    if (i < N_NODES) out[i] *= g_sinv;
}

// ---------------- launch ------------------------------------------------------
extern "C" void kernel_launch(void* const* d_in, const int* in_sizes, int n_in,
                              void* d_out, int out_size) {
    const float* x   = (const float*)d_in[0];
    const int*   ed  = (const int*)d_in[1];
    const float* w   = (const float*)d_in[2];
    const float* W1  = (const float*)d_in[3];
    const float* b1  = (const float*)d_in[4];
    const float* W2  = (const float*)d_in[5];
    const float* b2  = (const float*)d_in[6];
    const float* W3  = (const float*)d_in[7];
    const float* b3  = (const float*)d_in[8];
    const float* A2w = (const float*)d_in[9];
    const float* A2b = (const float*)d_in[10];
    float* out = (float*)d_out;

    (void)in_sizes; (void)n_in; (void)out_size;

    k_detect<<<1, 32>>>(ed);
    k_init<<<(N_NODES + 255) / 256, 256>>>();
    k_deg<<<N_EDGES / 256, 256>>>(ed, w);
    k_dinv<<<(N_NODES + 255) / 256, 256>>>();
    k_norm<<<N_EDGES / 256, 256>>>(w);

    k_lin1<<<N_NODES / 16, 256>>>(x, W1, b1);
    k_agg16<1><<<(N_EDGES * 4) / 256, 256>>>();

    k_lin2<<<N_NODES / 16, 256>>>(W2, b2);
    k_agg16<2><<<(N_EDGES * 4) / 256, 256>>>();

    k_lin3<<<(N_NODES + 255) / 256, 256>>>(W3, b3, out);
    k_agg3<<<N_EDGES / 256, 256>>>(out);

    k_max<<<128, 256>>>(out);
    k_maxfin<<<1, 128>>>();
    k_exp<<<128, 256>>>(out);
    k_sumfin<<<1, 128>>>(A2w, A2b, out);
    k_scale<<<(N_NODES + 255) / 256, 256>>>(out);
}